// round 13
// baseline (speedup 1.0000x reference)
#include <cuda_runtime.h>
#include <cstdint>

// Problem constants
#define BN 4
#define CC 256
#define SS 2304
#define NH 8
#define DD 32
#define TC 768

// Scratch (allocation-free rule: __device__ globals)
__device__ __align__(16) uint16_t g_xt[BN * SS * CC];      // x transposed, bf16 [b][s][c]
__device__ __align__(16) uint16_t g_wq[TC * CC];           // qkv_w bf16 [n][k]
__device__ __align__(16) uint16_t g_wp[CC * CC];           // proj_w bf16 [n][k]
__device__ __align__(16) uint16_t g_q[BN * NH * SS * DD];  // bf16, pre-scaled
__device__ __align__(16) uint16_t g_k[BN * NH * SS * DD];  // bf16
__device__ __align__(16) uint16_t g_v[BN * NH * SS * DD];  // bf16
__device__ __align__(16) uint16_t g_o[BN * SS * CC];       // bf16 [b][s][c] attn out

// ---- helpers ----------------------------------------------------------------
__device__ __forceinline__ uint32_t packbf(float lo, float hi) {
  uint32_t d;
  asm("cvt.rn.bf16x2.f32 %0, %1, %2;" : "=r"(d) : "f"(hi), "f"(lo));
  return d;
}
// two bf16 exp2's in one MUFU op (sm_90+)
__device__ __forceinline__ uint32_t ex2bf2(uint32_t x) {
  uint32_t y;
  asm("ex2.approx.ftz.bf16x2 %0, %1;" : "=r"(y) : "r"(x));
  return y;
}
// exact bf16x2 -> two fp32 (bf16 widening is exact)
__device__ __forceinline__ float bflo(uint32_t w) {
  return __uint_as_float(w << 16);
}
__device__ __forceinline__ float bfhi(uint32_t w) {
  return __uint_as_float(w & 0xffff0000u);
}
__device__ __forceinline__ void mma_bf16(float c[4], uint32_t a0, uint32_t a1,
                                         uint32_t a2, uint32_t a3,
                                         uint32_t b0, uint32_t b1) {
  asm volatile(
      "mma.sync.aligned.m16n8k16.row.col.f32.bf16.bf16.f32 "
      "{%0,%1,%2,%3}, {%4,%5,%6,%7}, {%8,%9}, {%0,%1,%2,%3};"
      : "+f"(c[0]), "+f"(c[1]), "+f"(c[2]), "+f"(c[3])
      : "r"(a0), "r"(a1), "r"(a2), "r"(a3), "r"(b0), "r"(b1));
}
__device__ __forceinline__ void ldmx2(uint32_t& r0, uint32_t& r1, uint32_t a) {
  asm volatile("ldmatrix.sync.aligned.m8n8.x2.shared.b16 {%0,%1}, [%2];"
               : "=r"(r0), "=r"(r1) : "r"(a));
}
__device__ __forceinline__ void ldmx2t(uint32_t& r0, uint32_t& r1, uint32_t a) {
  asm volatile("ldmatrix.sync.aligned.m8n8.x2.trans.shared.b16 {%0,%1}, [%2];"
               : "=r"(r0), "=r"(r1) : "r"(a));
}
__device__ __forceinline__ void ldmx4(uint32_t& r0, uint32_t& r1, uint32_t& r2,
                                      uint32_t& r3, uint32_t a) {
  asm volatile("ldmatrix.sync.aligned.m8n8.x4.shared.b16 {%0,%1,%2,%3}, [%4];"
               : "=r"(r0), "=r"(r1), "=r"(r2), "=r"(r3) : "r"(a));
}
__device__ __forceinline__ void cpa16(uint32_t dst, const void* src) {
  asm volatile("cp.async.ca.shared.global [%0], [%1], 16;"
               :: "r"(dst), "l"(src));
}
#define CP_COMMIT() asm volatile("cp.async.commit_group;")
#define CP_WAIT0()  asm volatile("cp.async.wait_group 0;")

// ---------------------------------------------------------------------------
// Prep A: transpose-convert x [b][c][s] fp32 -> g_xt [b][s][c] bf16.
// ---------------------------------------------------------------------------
__global__ __launch_bounds__(256) void cvt_x_kernel(const float* __restrict__ x) {
  __shared__ float t[32][33];
  int b  = blockIdx.z;
  int s0 = blockIdx.x * 32;
  int c0 = blockIdx.y * 32;
  int tx = threadIdx.x, ty = threadIdx.y;
  const float* xb = x + (size_t)b * CC * SS;
#pragma unroll
  for (int i = 0; i < 4; i++)
    t[ty + 8 * i][tx] = xb[(size_t)(c0 + ty + 8 * i) * SS + s0 + tx];
  __syncthreads();
  uint16_t* dst = g_xt + (size_t)b * SS * CC;
#pragma unroll
  for (int i = 0; i < 4; i++) {
    float v = t[tx][ty + 8 * i];
    uint32_t p = packbf(v, v);
    dst[(size_t)(s0 + ty + 8 * i) * CC + c0 + tx] = (uint16_t)(p & 0xffffu);
  }
}

// Prep B: weights fp32 -> bf16.
__global__ __launch_bounds__(256) void cvt_w_kernel(
    const float* __restrict__ qkv_w, const float* __restrict__ proj_w) {
  int j = blockIdx.x * 256 + threadIdx.x;
  if (j < TC * CC / 2)
    ((uint32_t*)g_wq)[j] = packbf(qkv_w[2 * j], qkv_w[2 * j + 1]);
  if (j < CC * CC / 2)
    ((uint32_t*)g_wp)[j] = packbf(proj_w[2 * j], proj_w[2 * j + 1]);
}

// ---------------------------------------------------------------------------
// Kernel 1: QKV projection, bf16 mma + ldmatrix, cp.async double-buffered.
// All panel ldmatrix hoisted ahead of the mma block (ILP / latency hiding).
// Grid: (BN*18, 12), 256 threads.
// ---------------------------------------------------------------------------
__global__ __launch_bounds__(256) void qkv_gemm_kernel(
    const float* __restrict__ bias) {
  __shared__ __align__(16) uint16_t As[2][128][40];
  __shared__ __align__(16) uint16_t Bs[2][64][40];
  int tid = threadIdx.x;
  int warp = tid >> 5, lane = tid & 31;
  int g = lane >> 2, tig = lane & 3;
  int wm = (warp & 3) * 32, wn = (warp >> 2) * 32;
  int bx = blockIdx.x;
  int b  = bx / 18;
  int m0 = (bx % 18) * 128;
  int n0 = blockIdx.y * 64;
  const uint16_t* A = g_xt + (size_t)b * SS * CC;

  uint32_t as0 = (uint32_t)__cvta_generic_to_shared(&As[0][0][0]);
  uint32_t bs0 = (uint32_t)__cvta_generic_to_shared(&Bs[0][0][0]);

  float c[2][4][4];
#pragma unroll
  for (int mt = 0; mt < 2; mt++)
#pragma unroll
    for (int nt = 0; nt < 4; nt++)
#pragma unroll
      for (int j = 0; j < 4; j++) c[mt][nt][j] = 0.f;

#define QKV_ISSUE(p, k0)                                                      \
  do {                                                                        \
    _Pragma("unroll") for (int i_ = 0; i_ < 2; i_++) {                        \
      int f_ = tid + i_ * 256;                                                \
      int m_ = f_ >> 2, cq_ = f_ & 3;                                         \
      cpa16(as0 + (p) * 10240u + (uint32_t)(m_ * 80 + cq_ * 16),              \
            &A[(size_t)(m0 + m_) * CC + (k0) + cq_ * 8]);                     \
    }                                                                         \
    {                                                                         \
      int n_ = tid >> 2, kq_ = tid & 3;                                       \
      cpa16(bs0 + (p) * 5120u + (uint32_t)(n_ * 80 + kq_ * 16),               \
            &g_wq[(size_t)(n0 + n_) * CC + (k0) + kq_ * 8]);                  \
    }                                                                         \
    CP_COMMIT();                                                              \
  } while (0)

  QKV_ISSUE(0, 0);
  for (int it = 0; it < 8; it++) {
    int p = it & 1;
    CP_WAIT0();
    __syncthreads();
    if (it < 7) QKV_ISSUE(p ^ 1, (it + 1) * 32);
    uint32_t ab = as0 + (uint32_t)p * 10240u;
    uint32_t bb = bs0 + (uint32_t)p * 5120u;
    // hoist ALL fragment loads for this panel (2 ks steps)
    uint32_t a[2][2][4];   // [ks][mt][4]
    uint32_t bf[2][4][2];  // [ks][nt][2]
#pragma unroll
    for (int ks = 0; ks < 2; ks++) {
      uint32_t kbyte = ks * 32;
#pragma unroll
      for (int mt = 0; mt < 2; mt++) {
        uint32_t ra = ab + (uint32_t)(wm + mt * 16 + (lane & 15)) * 80 +
                      kbyte + ((lane >> 4) & 1) * 16;
        ldmx4(a[ks][mt][0], a[ks][mt][1], a[ks][mt][2], a[ks][mt][3], ra);
      }
#pragma unroll
      for (int nt = 0; nt < 4; nt++) {
        uint32_t rb = bb + (uint32_t)(wn + nt * 8 + (lane & 7)) * 80 +
                      kbyte + ((lane >> 3) & 1) * 16;
        ldmx2(bf[ks][nt][0], bf[ks][nt][1], rb);
      }
    }
#pragma unroll
    for (int ks = 0; ks < 2; ks++)
#pragma unroll
      for (int mt = 0; mt < 2; mt++)
#pragma unroll
        for (int nt = 0; nt < 4; nt++)
          mma_bf16(c[mt][nt], a[ks][mt][0], a[ks][mt][1], a[ks][mt][2],
                   a[ks][mt][3], bf[ks][nt][0], bf[ks][nt][1]);
    __syncthreads();
  }
#undef QKV_ISSUE

  const float scale = 0.25503489458333f;   // 32^-0.5 * log2(e)
  int nb = n0 + wn;
  int which = nb / CC;
  int hr = nb % CC;
  int h = hr >> 5;
  uint16_t* dst = (which == 0) ? g_q : (which == 1) ? g_k : g_v;
  float sc = (which == 0) ? scale : 1.f;
  long base = ((long)(b * NH + h) * SS + m0 + wm) * DD;
#pragma unroll
  for (int mt = 0; mt < 2; mt++) {
#pragma unroll
    for (int nt = 0; nt < 4; nt++) {
      int d = nt * 8 + 2 * tig;
      float b0 = bias[nb + d], b1 = bias[nb + d + 1];
      uint32_t w0 = packbf((c[mt][nt][0] + b0) * sc, (c[mt][nt][1] + b1) * sc);
      uint32_t w1 = packbf((c[mt][nt][2] + b0) * sc, (c[mt][nt][3] + b1) * sc);
      *(uint32_t*)&dst[base + (long)(mt * 16 + g) * DD + d] = w0;
      *(uint32_t*)&dst[base + (long)(mt * 16 + g + 8) * DD + d] = w1;
    }
  }
}

// ---------------------------------------------------------------------------
// Kernel 2: flash attention. Warp q-tile 32 (2 m-tiles). No-shift softmax:
// p = 2^s via ex2.approx.ftz.bf16x2. l accumulated in fp32 by EXACT bf16x2
// unpack (shift/mask reinterpret) + FADD on the idle alu/fma pipes — the
// ones-column mma (11% of tensor work) is gone. PV back to 4 n-tiles.
// Fragment loads batched ahead of mma groups. Grid: (SS/256, B*NH), 256 thr.
// ---------------------------------------------------------------------------
__global__ __launch_bounds__(256) void attn_kernel() {
  __shared__ __align__(16) uint32_t KsW[2][1280];   // 5120 B per buffer
  __shared__ __align__(16) uint32_t VsW[2][1280];
  int bh   = blockIdx.y;
  int tid  = threadIdx.x;
  int lane = tid & 31;
  int g = lane >> 2, tig = lane & 3;
  int q0 = blockIdx.x * 256 + (tid >> 5) * 32;

  uint32_t ks0 = (uint32_t)__cvta_generic_to_shared(&KsW[0][0]);
  uint32_t vs0 = (uint32_t)__cvta_generic_to_shared(&VsW[0][0]);
  const char* Kg = (const char*)(g_k) + (size_t)(bh * SS) * 64;  // 64B/row
  const char* Vg = (const char*)(g_v) + (size_t)(bh * SS) * 64;

  // Q A-fragments for 2 m-tiles (rows q0+mt*16+{g,g+8})
  const uint32_t* Qw = (const uint32_t*)(g_q) + (size_t)(bh * SS + q0) * 16;
  uint32_t qa[2][2][4];
#pragma unroll
  for (int mt = 0; mt < 2; mt++)
#pragma unroll
    for (int kc = 0; kc < 2; kc++) {
      int r = mt * 16;
      qa[mt][kc][0] = Qw[(r + g) * 16 + kc * 8 + tig];
      qa[mt][kc][1] = Qw[(r + g + 8) * 16 + kc * 8 + tig];
      qa[mt][kc][2] = Qw[(r + g) * 16 + kc * 8 + tig + 4];
      qa[mt][kc][3] = Qw[(r + g + 8) * 16 + kc * 8 + tig + 4];
    }

  float o[2][4][4];
#pragma unroll
  for (int mt = 0; mt < 2; mt++)
#pragma unroll
    for (int i = 0; i < 4; i++)
#pragma unroll
      for (int j = 0; j < 4; j++) o[mt][i][j] = 0.f;
  float l0[2] = {0.f, 0.f}, l1[2] = {0.f, 0.f};

  uint32_t qk_row0 = (uint32_t)(lane & 7) * 80 + ((lane >> 3) & 1) * 16;
  uint32_t pv_row0 = (uint32_t)(lane & 15) * 80;

#define ATT_ISSUE(p, t0)                                                      \
  do {                                                                        \
    int row_ = tid >> 2, cq_ = tid & 3;                                       \
    uint32_t so_ = (uint32_t)(row_ * 80 + cq_ * 16);                          \
    size_t go_ = (size_t)((t0) + row_) * 64 + cq_ * 16;                       \
    cpa16(ks0 + (p) * 5120u + so_, Kg + go_);                                 \
    cpa16(vs0 + (p) * 5120u + so_, Vg + go_);                                 \
    CP_COMMIT();                                                              \
  } while (0)

  ATT_ISSUE(0, 0);
  for (int it = 0; it < SS / 64; it++) {
    int p = it & 1;
    CP_WAIT0();
    __syncthreads();
    if (it < SS / 64 - 1) ATT_ISSUE(p ^ 1, (it + 1) * 64);

    uint32_t qk_row = ks0 + (uint32_t)p * 5120u + qk_row0;
    uint32_t pv_row = vs0 + (uint32_t)p * 5120u + pv_row0;

    // ---- scores + p = 2^s; K frags shared across m-tiles ----
    uint32_t pa[2][4][4];
#pragma unroll
    for (int nt = 0; nt < 8; nt++) {
      float s[2][4];
#pragma unroll
      for (int mt = 0; mt < 2; mt++) {
        s[mt][0] = 0.f; s[mt][1] = 0.f; s[mt][2] = 0.f; s[mt][3] = 0.f;
      }
      uint32_t ra = qk_row + (uint32_t)(nt * 8) * 80;
      uint32_t b00, b01, b10, b11;
      ldmx2(b00, b01, ra);
      ldmx2(b10, b11, ra + 32);
      mma_bf16(s[0], qa[0][0][0], qa[0][0][1], qa[0][0][2], qa[0][0][3], b00, b01);
      mma_bf16(s[1], qa[1][0][0], qa[1][0][1], qa[1][0][2], qa[1][0][3], b00, b01);
      mma_bf16(s[0], qa[0][1][0], qa[0][1][1], qa[0][1][2], qa[0][1][3], b10, b11);
      mma_bf16(s[1], qa[1][1][0], qa[1][1][1], qa[1][1][2], qa[1][1][3], b10, b11);
#pragma unroll
      for (int mt = 0; mt < 2; mt++) {
        uint32_t w0 = ex2bf2(packbf(s[mt][0], s[mt][1]));
        uint32_t w1 = ex2bf2(packbf(s[mt][2], s[mt][3]));
        pa[mt][nt >> 1][(nt & 1) * 2]     = w0;
        pa[mt][nt >> 1][(nt & 1) * 2 + 1] = w1;
        l0[mt] += bflo(w0) + bfhi(w0);   // exact bf16 widening
        l1[mt] += bflo(w1) + bfhi(w1);
      }
    }

    // ---- O += P * V : batch all 4 V frags per kc, then 8 mma ----
#pragma unroll
    for (int kc = 0; kc < 4; kc++) {
      uint32_t ra = pv_row + (uint32_t)(kc * 16) * 80;
      uint32_t vb[4][2];
#pragma unroll
      for (int nt = 0; nt < 4; nt++)
        ldmx2t(vb[nt][0], vb[nt][1], ra + nt * 16);
#pragma unroll
      for (int nt = 0; nt < 4; nt++) {
        mma_bf16(o[0][nt], pa[0][kc][0], pa[0][kc][1], pa[0][kc][2],
                 pa[0][kc][3], vb[nt][0], vb[nt][1]);
        mma_bf16(o[1][nt], pa[1][kc][0], pa[1][kc][1], pa[1][kc][2],
                 pa[1][kc][3], vb[nt][0], vb[nt][1]);
      }
    }
    __syncthreads();
  }
#undef ATT_ISSUE

  int b = bh / NH, h = bh % NH;
#pragma unroll
  for (int mt = 0; mt < 2; mt++) {
    float a0 = l0[mt], a1 = l1[mt];
    a0 += __shfl_xor_sync(0xffffffffu, a0, 1);
    a0 += __shfl_xor_sync(0xffffffffu, a0, 2);
    a1 += __shfl_xor_sync(0xffffffffu, a1, 1);
    a1 += __shfl_xor_sync(0xffffffffu, a1, 2);
    float inv0 = 1.f / a0, inv1 = 1.f / a1;
    int r0 = q0 + mt * 16 + g, r1 = r0 + 8;
    uint32_t* O0 = (uint32_t*)(g_o + ((size_t)(b * SS + r0) * NH + h) * DD);
    uint32_t* O1 = (uint32_t*)(g_o + ((size_t)(b * SS + r1) * NH + h) * DD);
#pragma unroll
    for (int nt = 0; nt < 4; nt++) {
      O0[nt * 4 + tig] = packbf(o[mt][nt][0] * inv0, o[mt][nt][1] * inv0);
      O1[nt * 4 + tig] = packbf(o[mt][nt][2] * inv1, o[mt][nt][3] * inv1);
    }
  }
}

// ---------------------------------------------------------------------------
// Kernel 3: output projection, bf16 mma + ldmatrix, hoisted panel loads.
// Grid: (18, 4, BN), 256 threads.
// ---------------------------------------------------------------------------
__global__ __launch_bounds__(256) void proj_kernel(
    const float* __restrict__ x, const float* __restrict__ bias,
    float* __restrict__ out) {
  __shared__ __align__(16) uint16_t As[2][128][40];
  __shared__ __align__(16) uint16_t Bs[2][64][40];
  int tid = threadIdx.x;
  int warp = tid >> 5, lane = tid & 31;
  int g = lane >> 2, tig = lane & 3;
  int wm = (warp & 3) * 32, wn = (warp >> 2) * 32;
  int b  = blockIdx.z;
  int m0 = blockIdx.x * 128;
  int n0 = blockIdx.y * 64;
  const uint16_t* A = g_o + (size_t)b * SS * CC;

  uint32_t as0 = (uint32_t)__cvta_generic_to_shared(&As[0][0][0]);
  uint32_t bs0 = (uint32_t)__cvta_generic_to_shared(&Bs[0][0][0]);

  float c[2][4][4];
#pragma unroll
  for (int mt = 0; mt < 2; mt++)
#pragma unroll
    for (int nt = 0; nt < 4; nt++)
#pragma unroll
      for (int j = 0; j < 4; j++) c[mt][nt][j] = 0.f;

#define PROJ_ISSUE(p, k0)                                                     \
  do {                                                                        \
    _Pragma("unroll") for (int i_ = 0; i_ < 2; i_++) {                        \
      int f_ = tid + i_ * 256;                                                \
      int m_ = f_ >> 2, cq_ = f_ & 3;                                         \
      cpa16(as0 + (p) * 10240u + (uint32_t)(m_ * 80 + cq_ * 16),              \
            &A[(size_t)(m0 + m_) * CC + (k0) + cq_ * 8]);                     \
    }                                                                         \
    {                                                                         \
      int n_ = tid >> 2, kq_ = tid & 3;                                       \
      cpa16(bs0 + (p) * 5120u + (uint32_t)(n_ * 80 + kq_ * 16),               \
            &g_wp[(size_t)(n0 + n_) * CC + (k0) + kq_ * 8]);                  \
    }                                                                         \
    CP_COMMIT();                                                              \
  } while (0)

  PROJ_ISSUE(0, 0);
  for (int it = 0; it < 8; it++) {
    int p = it & 1;
    CP_WAIT0();
    __syncthreads();
    if (it < 7) PROJ_ISSUE(p ^ 1, (it + 1) * 32);
    uint32_t ab = as0 + (uint32_t)p * 10240u;
    uint32_t bb = bs0 + (uint32_t)p * 5120u;
    uint32_t a[2][2][4];
    uint32_t bf[2][4][2];
#pragma unroll
    for (int ks = 0; ks < 2; ks++) {
      uint32_t kbyte = ks * 32;
#pragma unroll
      for (int mt = 0; mt < 2; mt++) {
        uint32_t ra = ab + (uint32_t)(wm + mt * 16 + (lane & 15)) * 80 +
                      kbyte + ((lane >> 4) & 1) * 16;
        ldmx4(a[ks][mt][0], a[ks][mt][1], a[ks][mt][2], a[ks][mt][3], ra);
      }
#pragma unroll
      for (int nt = 0; nt < 4; nt++) {
        uint32_t rb = bb + (uint32_t)(wn + nt * 8 + (lane & 7)) * 80 +
                      kbyte + ((lane >> 3) & 1) * 16;
        ldmx2(bf[ks][nt][0], bf[ks][nt][1], rb);
      }
    }
#pragma unroll
    for (int ks = 0; ks < 2; ks++)
#pragma unroll
      for (int mt = 0; mt < 2; mt++)
#pragma unroll
        for (int nt = 0; nt < 4; nt++)
          mma_bf16(c[mt][nt], a[ks][mt][0], a[ks][mt][1], a[ks][mt][2],
                   a[ks][mt][3], bf[ks][nt][0], bf[ks][nt][1]);
    __syncthreads();
  }
#undef PROJ_ISSUE

#pragma unroll
  for (int nt = 0; nt < 4; nt++) {
    int n = n0 + wn + nt * 8 + 2 * tig;
    float b0 = bias[n], b1 = bias[n + 1];
    long col0 = (long)(b * CC + n) * SS;
    long col1 = col0 + SS;
#pragma unroll
    for (int mt = 0; mt < 2; mt++) {
      int s = m0 + wm + mt * 16 + g;
      out[col0 + s]     = c[mt][nt][0] + b0 + x[col0 + s];
      out[col1 + s]     = c[mt][nt][1] + b1 + x[col1 + s];
      out[col0 + s + 8] = c[mt][nt][2] + b0 + x[col0 + s + 8];
      out[col1 + s + 8] = c[mt][nt][3] + b1 + x[col1 + s + 8];
    }
  }
}

// ---------------------------------------------------------------------------
extern "C" void kernel_launch(void* const* d_in, const int* in_sizes, int n_in,
                              void* d_out, int out_size) {
  const float* x      = (const float*)d_in[0];
  const float* qkv_w  = (const float*)d_in[1];
  const float* qkv_b  = (const float*)d_in[2];
  const float* proj_w = (const float*)d_in[3];
  const float* proj_b = (const float*)d_in[4];
  float* out = (float*)d_out;

  cvt_x_kernel<<<dim3(SS / 32, CC / 32, BN), dim3(32, 8)>>>(x);
  cvt_w_kernel<<<dim3((TC * CC / 2 + 255) / 256), 256>>>(qkv_w, proj_w);
  qkv_gemm_kernel<<<dim3(BN * 18, TC / 64), 256>>>(qkv_b);
  attn_kernel<<<dim3(SS / 256, BN * NH), 256>>>();
  proj_kernel<<<dim3(18, CC / 64, BN), 256>>>(x, proj_b, out);
}

// round 14
// speedup vs baseline: 1.0386x; 1.0386x over previous
#include <cuda_runtime.h>
#include <cstdint>

// Problem constants
#define BN 4
#define CC 256
#define SS 2304
#define NH 8
#define DD 32
#define TC 768

// Scratch (allocation-free rule: __device__ globals)
__device__ __align__(16) uint16_t g_xt[BN * SS * CC];      // x transposed, bf16 [b][s][c]
__device__ __align__(16) uint16_t g_wq[TC * CC];           // qkv_w bf16 [n][k]
__device__ __align__(16) uint16_t g_wp[CC * CC];           // proj_w bf16 [n][k]
__device__ __align__(16) uint16_t g_q[BN * NH * SS * DD];  // bf16, pre-scaled
__device__ __align__(16) uint16_t g_k[BN * NH * SS * DD];  // bf16
__device__ __align__(16) uint16_t g_v[BN * NH * SS * DD];  // bf16
__device__ __align__(16) uint16_t g_o[BN * SS * CC];       // bf16 [b][s][c] attn out

// ---- helpers ----------------------------------------------------------------
__device__ __forceinline__ uint32_t packbf(float lo, float hi) {
  uint32_t d;
  asm("cvt.rn.bf16x2.f32 %0, %1, %2;" : "=r"(d) : "f"(hi), "f"(lo));
  return d;
}
// two bf16 exp2's in one MUFU op (sm_90+)
__device__ __forceinline__ uint32_t ex2bf2(uint32_t x) {
  uint32_t y;
  asm("ex2.approx.ftz.bf16x2 %0, %1;" : "=r"(y) : "r"(x));
  return y;
}
__device__ __forceinline__ void mma_bf16(float c[4], uint32_t a0, uint32_t a1,
                                         uint32_t a2, uint32_t a3,
                                         uint32_t b0, uint32_t b1) {
  asm volatile(
      "mma.sync.aligned.m16n8k16.row.col.f32.bf16.bf16.f32 "
      "{%0,%1,%2,%3}, {%4,%5,%6,%7}, {%8,%9}, {%0,%1,%2,%3};"
      : "+f"(c[0]), "+f"(c[1]), "+f"(c[2]), "+f"(c[3])
      : "r"(a0), "r"(a1), "r"(a2), "r"(a3), "r"(b0), "r"(b1));
}
__device__ __forceinline__ void ldmx2(uint32_t& r0, uint32_t& r1, uint32_t a) {
  asm volatile("ldmatrix.sync.aligned.m8n8.x2.shared.b16 {%0,%1}, [%2];"
               : "=r"(r0), "=r"(r1) : "r"(a));
}
__device__ __forceinline__ void ldmx2t(uint32_t& r0, uint32_t& r1, uint32_t a) {
  asm volatile("ldmatrix.sync.aligned.m8n8.x2.trans.shared.b16 {%0,%1}, [%2];"
               : "=r"(r0), "=r"(r1) : "r"(a));
}
__device__ __forceinline__ void ldmx4(uint32_t& r0, uint32_t& r1, uint32_t& r2,
                                      uint32_t& r3, uint32_t a) {
  asm volatile("ldmatrix.sync.aligned.m8n8.x4.shared.b16 {%0,%1,%2,%3}, [%4];"
               : "=r"(r0), "=r"(r1), "=r"(r2), "=r"(r3) : "r"(a));
}
__device__ __forceinline__ void cpa16(uint32_t dst, const void* src) {
  asm volatile("cp.async.ca.shared.global [%0], [%1], 16;"
               :: "r"(dst), "l"(src));
}
#define CP_COMMIT() asm volatile("cp.async.commit_group;")
#define CP_WAIT0()  asm volatile("cp.async.wait_group 0;")

// ---------------------------------------------------------------------------
// Prep A: transpose-convert x [b][c][s] fp32 -> g_xt [b][s][c] bf16.
// ---------------------------------------------------------------------------
__global__ __launch_bounds__(256) void cvt_x_kernel(const float* __restrict__ x) {
  __shared__ float t[32][33];
  int b  = blockIdx.z;
  int s0 = blockIdx.x * 32;
  int c0 = blockIdx.y * 32;
  int tx = threadIdx.x, ty = threadIdx.y;
  const float* xb = x + (size_t)b * CC * SS;
#pragma unroll
  for (int i = 0; i < 4; i++)
    t[ty + 8 * i][tx] = xb[(size_t)(c0 + ty + 8 * i) * SS + s0 + tx];
  __syncthreads();
  uint16_t* dst = g_xt + (size_t)b * SS * CC;
#pragma unroll
  for (int i = 0; i < 4; i++) {
    float v = t[tx][ty + 8 * i];
    uint32_t p = packbf(v, v);
    dst[(size_t)(s0 + ty + 8 * i) * CC + c0 + tx] = (uint16_t)(p & 0xffffu);
  }
}

// Prep B: weights fp32 -> bf16.
__global__ __launch_bounds__(256) void cvt_w_kernel(
    const float* __restrict__ qkv_w, const float* __restrict__ proj_w) {
  int j = blockIdx.x * 256 + threadIdx.x;
  if (j < TC * CC / 2)
    ((uint32_t*)g_wq)[j] = packbf(qkv_w[2 * j], qkv_w[2 * j + 1]);
  if (j < CC * CC / 2)
    ((uint32_t*)g_wp)[j] = packbf(proj_w[2 * j], proj_w[2 * j + 1]);
}

// ---------------------------------------------------------------------------
// Kernel 1: QKV projection, bf16 mma + ldmatrix, cp.async double-buffered
// (exact R12 version). Grid: (BN*18, 12), 256 threads.
// ---------------------------------------------------------------------------
__global__ __launch_bounds__(256) void qkv_gemm_kernel(
    const float* __restrict__ bias) {
  __shared__ __align__(16) uint16_t As[2][128][40];
  __shared__ __align__(16) uint16_t Bs[2][64][40];
  int tid = threadIdx.x;
  int warp = tid >> 5, lane = tid & 31;
  int g = lane >> 2, tig = lane & 3;
  int wm = (warp & 3) * 32, wn = (warp >> 2) * 32;
  int bx = blockIdx.x;
  int b  = bx / 18;
  int m0 = (bx % 18) * 128;
  int n0 = blockIdx.y * 64;
  const uint16_t* A = g_xt + (size_t)b * SS * CC;

  uint32_t as0 = (uint32_t)__cvta_generic_to_shared(&As[0][0][0]);
  uint32_t bs0 = (uint32_t)__cvta_generic_to_shared(&Bs[0][0][0]);

  float c[2][4][4];
#pragma unroll
  for (int mt = 0; mt < 2; mt++)
#pragma unroll
    for (int nt = 0; nt < 4; nt++)
#pragma unroll
      for (int j = 0; j < 4; j++) c[mt][nt][j] = 0.f;

#define QKV_ISSUE(p, k0)                                                      \
  do {                                                                        \
    _Pragma("unroll") for (int i_ = 0; i_ < 2; i_++) {                        \
      int f_ = tid + i_ * 256;                                                \
      int m_ = f_ >> 2, cq_ = f_ & 3;                                         \
      cpa16(as0 + (p) * 10240u + (uint32_t)(m_ * 80 + cq_ * 16),              \
            &A[(size_t)(m0 + m_) * CC + (k0) + cq_ * 8]);                     \
    }                                                                         \
    {                                                                         \
      int n_ = tid >> 2, kq_ = tid & 3;                                       \
      cpa16(bs0 + (p) * 5120u + (uint32_t)(n_ * 80 + kq_ * 16),               \
            &g_wq[(size_t)(n0 + n_) * CC + (k0) + kq_ * 8]);                  \
    }                                                                         \
    CP_COMMIT();                                                              \
  } while (0)

  QKV_ISSUE(0, 0);
  for (int it = 0; it < 8; it++) {
    int p = it & 1;
    CP_WAIT0();
    __syncthreads();
    if (it < 7) QKV_ISSUE(p ^ 1, (it + 1) * 32);
    uint32_t ab = as0 + (uint32_t)p * 10240u;
    uint32_t bb = bs0 + (uint32_t)p * 5120u;
#pragma unroll
    for (int ks = 0; ks < 2; ks++) {
      uint32_t kbyte = ks * 32;
      uint32_t a[2][4];
#pragma unroll
      for (int mt = 0; mt < 2; mt++) {
        uint32_t ra = ab + (uint32_t)(wm + mt * 16 + (lane & 15)) * 80 +
                      kbyte + ((lane >> 4) & 1) * 16;
        ldmx4(a[mt][0], a[mt][1], a[mt][2], a[mt][3], ra);
      }
      uint32_t bf[4][2];
#pragma unroll
      for (int nt = 0; nt < 4; nt++) {
        uint32_t rb = bb + (uint32_t)(wn + nt * 8 + (lane & 7)) * 80 +
                      kbyte + ((lane >> 3) & 1) * 16;
        ldmx2(bf[nt][0], bf[nt][1], rb);
      }
#pragma unroll
      for (int mt = 0; mt < 2; mt++)
#pragma unroll
        for (int nt = 0; nt < 4; nt++)
          mma_bf16(c[mt][nt], a[mt][0], a[mt][1], a[mt][2], a[mt][3],
                   bf[nt][0], bf[nt][1]);
    }
    __syncthreads();
  }
#undef QKV_ISSUE

  const float scale = 0.25503489458333f;   // 32^-0.5 * log2(e)
  int nb = n0 + wn;
  int which = nb / CC;
  int hr = nb % CC;
  int h = hr >> 5;
  uint16_t* dst = (which == 0) ? g_q : (which == 1) ? g_k : g_v;
  float sc = (which == 0) ? scale : 1.f;
  long base = ((long)(b * NH + h) * SS + m0 + wm) * DD;
#pragma unroll
  for (int mt = 0; mt < 2; mt++) {
#pragma unroll
    for (int nt = 0; nt < 4; nt++) {
      int d = nt * 8 + 2 * tig;
      float b0 = bias[nb + d], b1 = bias[nb + d + 1];
      uint32_t w0 = packbf((c[mt][nt][0] + b0) * sc, (c[mt][nt][1] + b1) * sc);
      uint32_t w1 = packbf((c[mt][nt][2] + b0) * sc, (c[mt][nt][3] + b1) * sc);
      *(uint32_t*)&dst[base + (long)(mt * 16 + g) * DD + d] = w0;
      *(uint32_t*)&dst[base + (long)(mt * 16 + g + 8) * DD + d] = w1;
    }
  }
}

// ---------------------------------------------------------------------------
// Kernel 2: flash attention (R12 inner structure: ones-column l, bf16x2 ex2,
// no-shift softmax). K/V smem tiles DOUBLED to 128 keys, processed in two
// 64-key halves -> barriers and cp.async rounds halve (36 iters -> 18).
// Warp q-tile 32 (2 m-tiles), block q-tile 256. Grid: (SS/256, B*NH).
// ---------------------------------------------------------------------------
__global__ __launch_bounds__(256) void attn_kernel() {
  __shared__ __align__(16) uint32_t KsW[2][2560];   // 10240 B per buffer (128 rows)
  __shared__ __align__(16) uint32_t VsW[2][2560];
  int bh   = blockIdx.y;
  int tid  = threadIdx.x;
  int lane = tid & 31;
  int g = lane >> 2, tig = lane & 3;
  int q0 = blockIdx.x * 256 + (tid >> 5) * 32;

  uint32_t ks0 = (uint32_t)__cvta_generic_to_shared(&KsW[0][0]);
  uint32_t vs0 = (uint32_t)__cvta_generic_to_shared(&VsW[0][0]);
  const char* Kg = (const char*)(g_k) + (size_t)(bh * SS) * 64;  // 64B/row
  const char* Vg = (const char*)(g_v) + (size_t)(bh * SS) * 64;

  // V tail init: col 32 = 1.0bf16 (ones column for l), cols 33..39 = 0.
  // Fills only write word-cols 0..15 (64 B), so this survives the loop.
  for (int i = tid; i < 1024; i += 256) {
    int buf = i >> 9, j = i & 511, rw = j >> 2, wq = j & 3;
    VsW[buf][rw * 20 + 16 + wq] = (wq == 0) ? 0x3f80u : 0u;
  }

  // Q A-fragments for 2 m-tiles (rows q0+mt*16+{g,g+8})
  const uint32_t* Qw = (const uint32_t*)(g_q) + (size_t)(bh * SS + q0) * 16;
  uint32_t qa[2][2][4];
#pragma unroll
  for (int mt = 0; mt < 2; mt++)
#pragma unroll
    for (int kc = 0; kc < 2; kc++) {
      int r = mt * 16;
      qa[mt][kc][0] = Qw[(r + g) * 16 + kc * 8 + tig];
      qa[mt][kc][1] = Qw[(r + g + 8) * 16 + kc * 8 + tig];
      qa[mt][kc][2] = Qw[(r + g) * 16 + kc * 8 + tig + 4];
      qa[mt][kc][3] = Qw[(r + g + 8) * 16 + kc * 8 + tig + 4];
    }

  float o[2][5][4];   // n-tile 4 = ones column (row sums l at col 32)
#pragma unroll
  for (int mt = 0; mt < 2; mt++)
#pragma unroll
    for (int i = 0; i < 5; i++)
#pragma unroll
      for (int j = 0; j < 4; j++) o[mt][i][j] = 0.f;

  uint32_t qk_row0 = (uint32_t)(lane & 7) * 80 + ((lane >> 3) & 1) * 16;
  uint32_t pv_row0 = (uint32_t)(lane & 15) * 80;

  // fill 128 rows of K and V (2 x 16B chunks per thread per matrix)
#define ATT_ISSUE(p, t0)                                                      \
  do {                                                                        \
    _Pragma("unroll") for (int i_ = 0; i_ < 2; i_++) {                        \
      int f_ = tid + i_ * 256;            /* 0..511 */                        \
      int row_ = f_ >> 2, cq_ = f_ & 3;                                       \
      uint32_t so_ = (uint32_t)(row_ * 80 + cq_ * 16);                        \
      size_t go_ = (size_t)((t0) + row_) * 64 + cq_ * 16;                     \
      cpa16(ks0 + (p) * 10240u + so_, Kg + go_);                              \
      cpa16(vs0 + (p) * 10240u + so_, Vg + go_);                              \
    }                                                                         \
    CP_COMMIT();                                                              \
  } while (0)

  ATT_ISSUE(0, 0);
  for (int it = 0; it < SS / 128; it++) {
    int p = it & 1;
    CP_WAIT0();
    __syncthreads();
    if (it < SS / 128 - 1) ATT_ISSUE(p ^ 1, (it + 1) * 128);

#pragma unroll
    for (int half = 0; half < 2; half++) {
      uint32_t qk_row = ks0 + (uint32_t)p * 10240u + (uint32_t)(half * 64) * 80 + qk_row0;
      uint32_t pv_row = vs0 + (uint32_t)p * 10240u + (uint32_t)(half * 64) * 80 + pv_row0;

      // ---- scores + p = 2^s (bf16x2 MUFU); K frags shared across m-tiles ----
      uint32_t pa[2][4][4];
#pragma unroll
      for (int nt = 0; nt < 8; nt++) {
        float s[2][4];
#pragma unroll
        for (int mt = 0; mt < 2; mt++) {
          s[mt][0] = 0.f; s[mt][1] = 0.f; s[mt][2] = 0.f; s[mt][3] = 0.f;
        }
        uint32_t ra = qk_row + (uint32_t)(nt * 8) * 80;
#pragma unroll
        for (int kc = 0; kc < 2; kc++) {
          uint32_t b0, b1;
          ldmx2(b0, b1, ra + kc * 32);
          mma_bf16(s[0], qa[0][kc][0], qa[0][kc][1], qa[0][kc][2], qa[0][kc][3],
                   b0, b1);
          mma_bf16(s[1], qa[1][kc][0], qa[1][kc][1], qa[1][kc][2], qa[1][kc][3],
                   b0, b1);
        }
#pragma unroll
        for (int mt = 0; mt < 2; mt++) {
          pa[mt][nt >> 1][(nt & 1) * 2]     = ex2bf2(packbf(s[mt][0], s[mt][1]));
          pa[mt][nt >> 1][(nt & 1) * 2 + 1] = ex2bf2(packbf(s[mt][2], s[mt][3]));
        }
      }

      // ---- O += P * V (5 n-tiles: 4 data + ones column for l) ----
#pragma unroll
      for (int kc = 0; kc < 4; kc++) {
        uint32_t ra = pv_row + (uint32_t)(kc * 16) * 80;
#pragma unroll
        for (int nt = 0; nt < 5; nt++) {
          uint32_t b0, b1;
          ldmx2t(b0, b1, ra + nt * 16);
          mma_bf16(o[0][nt], pa[0][kc][0], pa[0][kc][1], pa[0][kc][2],
                   pa[0][kc][3], b0, b1);
          mma_bf16(o[1][nt], pa[1][kc][0], pa[1][kc][1], pa[1][kc][2],
                   pa[1][kc][3], b0, b1);
        }
      }
    }
    __syncthreads();
  }
#undef ATT_ISSUE

  int b = bh / NH, h = bh % NH;
  int src = lane & ~3;   // tig=0 lane of this quad (holds col 32 = l)
#pragma unroll
  for (int mt = 0; mt < 2; mt++) {
    float sl0 = __shfl_sync(0xffffffffu, o[mt][4][0], src);
    float sl1 = __shfl_sync(0xffffffffu, o[mt][4][2], src);
    float inv0 = 1.f / sl0, inv1 = 1.f / sl1;
    int r0 = q0 + mt * 16 + g, r1 = r0 + 8;
    uint32_t* O0 = (uint32_t*)(g_o + ((size_t)(b * SS + r0) * NH + h) * DD);
    uint32_t* O1 = (uint32_t*)(g_o + ((size_t)(b * SS + r1) * NH + h) * DD);
#pragma unroll
    for (int nt = 0; nt < 4; nt++) {
      O0[nt * 4 + tig] = packbf(o[mt][nt][0] * inv0, o[mt][nt][1] * inv0);
      O1[nt * 4 + tig] = packbf(o[mt][nt][2] * inv1, o[mt][nt][3] * inv1);
    }
  }
}

// ---------------------------------------------------------------------------
// Kernel 3: output projection, bf16 mma + ldmatrix (exact R12 version).
// Grid: (18, 4, BN), 256 threads.
// ---------------------------------------------------------------------------
__global__ __launch_bounds__(256) void proj_kernel(
    const float* __restrict__ x, const float* __restrict__ bias,
    float* __restrict__ out) {
  __shared__ __align__(16) uint16_t As[2][128][40];
  __shared__ __align__(16) uint16_t Bs[2][64][40];
  int tid = threadIdx.x;
  int warp = tid >> 5, lane = tid & 31;
  int g = lane >> 2, tig = lane & 3;
  int wm = (warp & 3) * 32, wn = (warp >> 2) * 32;
  int b  = blockIdx.z;
  int m0 = blockIdx.x * 128;
  int n0 = blockIdx.y * 64;
  const uint16_t* A = g_o + (size_t)b * SS * CC;

  uint32_t as0 = (uint32_t)__cvta_generic_to_shared(&As[0][0][0]);
  uint32_t bs0 = (uint32_t)__cvta_generic_to_shared(&Bs[0][0][0]);

  float c[2][4][4];
#pragma unroll
  for (int mt = 0; mt < 2; mt++)
#pragma unroll
    for (int nt = 0; nt < 4; nt++)
#pragma unroll
      for (int j = 0; j < 4; j++) c[mt][nt][j] = 0.f;

#define PROJ_ISSUE(p, k0)                                                     \
  do {                                                                        \
    _Pragma("unroll") for (int i_ = 0; i_ < 2; i_++) {                        \
      int f_ = tid + i_ * 256;                                                \
      int m_ = f_ >> 2, cq_ = f_ & 3;                                         \
      cpa16(as0 + (p) * 10240u + (uint32_t)(m_ * 80 + cq_ * 16),              \
            &A[(size_t)(m0 + m_) * CC + (k0) + cq_ * 8]);                     \
    }                                                                         \
    {                                                                         \
      int n_ = tid >> 2, kq_ = tid & 3;                                       \
      cpa16(bs0 + (p) * 5120u + (uint32_t)(n_ * 80 + kq_ * 16),               \
            &g_wp[(size_t)(n0 + n_) * CC + (k0) + kq_ * 8]);                  \
    }                                                                         \
    CP_COMMIT();                                                              \
  } while (0)

  PROJ_ISSUE(0, 0);
  for (int it = 0; it < 8; it++) {
    int p = it & 1;
    CP_WAIT0();
    __syncthreads();
    if (it < 7) PROJ_ISSUE(p ^ 1, (it + 1) * 32);
    uint32_t ab = as0 + (uint32_t)p * 10240u;
    uint32_t bb = bs0 + (uint32_t)p * 5120u;
#pragma unroll
    for (int ks = 0; ks < 2; ks++) {
      uint32_t kbyte = ks * 32;
      uint32_t a[2][4];
#pragma unroll
      for (int mt = 0; mt < 2; mt++) {
        uint32_t ra = ab + (uint32_t)(wm + mt * 16 + (lane & 15)) * 80 +
                      kbyte + ((lane >> 4) & 1) * 16;
        ldmx4(a[mt][0], a[mt][1], a[mt][2], a[mt][3], ra);
      }
      uint32_t bf[4][2];
#pragma unroll
      for (int nt = 0; nt < 4; nt++) {
        uint32_t rb = bb + (uint32_t)(wn + nt * 8 + (lane & 7)) * 80 +
                      kbyte + ((lane >> 3) & 1) * 16;
        ldmx2(bf[nt][0], bf[nt][1], rb);
      }
#pragma unroll
      for (int mt = 0; mt < 2; mt++)
#pragma unroll
        for (int nt = 0; nt < 4; nt++)
          mma_bf16(c[mt][nt], a[mt][0], a[mt][1], a[mt][2], a[mt][3],
                   bf[nt][0], bf[nt][1]);
    }
    __syncthreads();
  }
#undef PROJ_ISSUE

#pragma unroll
  for (int nt = 0; nt < 4; nt++) {
    int n = n0 + wn + nt * 8 + 2 * tig;
    float b0 = bias[n], b1 = bias[n + 1];
    long col0 = (long)(b * CC + n) * SS;
    long col1 = col0 + SS;
#pragma unroll
    for (int mt = 0; mt < 2; mt++) {
      int s = m0 + wm + mt * 16 + g;
      out[col0 + s]     = c[mt][nt][0] + b0 + x[col0 + s];
      out[col1 + s]     = c[mt][nt][1] + b1 + x[col1 + s];
      out[col0 + s + 8] = c[mt][nt][2] + b0 + x[col0 + s + 8];
      out[col1 + s + 8] = c[mt][nt][3] + b1 + x[col1 + s + 8];
    }
  }
}

// ---------------------------------------------------------------------------
extern "C" void kernel_launch(void* const* d_in, const int* in_sizes, int n_in,
                              void* d_out, int out_size) {
  const float* x      = (const float*)d_in[0];
  const float* qkv_w  = (const float*)d_in[1];
  const float* qkv_b  = (const float*)d_in[2];
  const float* proj_w = (const float*)d_in[3];
  const float* proj_b = (const float*)d_in[4];
  float* out = (float*)d_out;

  cvt_x_kernel<<<dim3(SS / 32, CC / 32, BN), dim3(32, 8)>>>(x);
  cvt_w_kernel<<<dim3((TC * CC / 2 + 255) / 256), 256>>>(qkv_w, proj_w);
  qkv_gemm_kernel<<<dim3(BN * 18, TC / 64), 256>>>(qkv_b);
  attn_kernel<<<dim3(SS / 256, BN * NH), 256>>>();
  proj_kernel<<<dim3(18, CC / 64, BN), 256>>>(x, proj_b, out);
}

// round 15
// speedup vs baseline: 1.0995x; 1.0586x over previous
#include <cuda_runtime.h>
#include <cstdint>

// Problem constants
#define BN 4
#define CC 256
#define SS 2304
#define NH 8
#define DD 32
#define TC 768

// Scratch (allocation-free rule: __device__ globals)
__device__ __align__(16) uint16_t g_xt[BN * SS * CC];      // x transposed, bf16 [b][s][c]
__device__ __align__(16) uint16_t g_wq[TC * CC];           // qkv_w bf16 [n][k]
__device__ __align__(16) uint16_t g_wp[CC * CC];           // proj_w bf16 [n][k]
__device__ __align__(16) uint16_t g_q[BN * NH * SS * DD];  // bf16, pre-scaled
__device__ __align__(16) uint16_t g_k[BN * NH * SS * DD];  // bf16
__device__ __align__(16) uint16_t g_v[BN * NH * SS * DD];  // bf16
__device__ __align__(16) uint16_t g_o[BN * SS * CC];       // bf16 [b][s][c] attn out

// ---- helpers ----------------------------------------------------------------
__device__ __forceinline__ uint32_t packbf(float lo, float hi) {
  uint32_t d;
  asm("cvt.rn.bf16x2.f32 %0, %1, %2;" : "=r"(d) : "f"(hi), "f"(lo));
  return d;
}
// two bf16 exp2's in one MUFU op (sm_90+)
__device__ __forceinline__ uint32_t ex2bf2(uint32_t x) {
  uint32_t y;
  asm("ex2.approx.ftz.bf16x2 %0, %1;" : "=r"(y) : "r"(x));
  return y;
}
__device__ __forceinline__ void mma_bf16(float c[4], uint32_t a0, uint32_t a1,
                                         uint32_t a2, uint32_t a3,
                                         uint32_t b0, uint32_t b1) {
  asm volatile(
      "mma.sync.aligned.m16n8k16.row.col.f32.bf16.bf16.f32 "
      "{%0,%1,%2,%3}, {%4,%5,%6,%7}, {%8,%9}, {%0,%1,%2,%3};"
      : "+f"(c[0]), "+f"(c[1]), "+f"(c[2]), "+f"(c[3])
      : "r"(a0), "r"(a1), "r"(a2), "r"(a3), "r"(b0), "r"(b1));
}
__device__ __forceinline__ void ldmx2(uint32_t& r0, uint32_t& r1, uint32_t a) {
  asm volatile("ldmatrix.sync.aligned.m8n8.x2.shared.b16 {%0,%1}, [%2];"
               : "=r"(r0), "=r"(r1) : "r"(a));
}
__device__ __forceinline__ void ldmx2t(uint32_t& r0, uint32_t& r1, uint32_t a) {
  asm volatile("ldmatrix.sync.aligned.m8n8.x2.trans.shared.b16 {%0,%1}, [%2];"
               : "=r"(r0), "=r"(r1) : "r"(a));
}
__device__ __forceinline__ void ldmx4(uint32_t& r0, uint32_t& r1, uint32_t& r2,
                                      uint32_t& r3, uint32_t a) {
  asm volatile("ldmatrix.sync.aligned.m8n8.x4.shared.b16 {%0,%1,%2,%3}, [%4];"
               : "=r"(r0), "=r"(r1), "=r"(r2), "=r"(r3) : "r"(a));
}
__device__ __forceinline__ void cpa16(uint32_t dst, const void* src) {
  asm volatile("cp.async.ca.shared.global [%0], [%1], 16;"
               :: "r"(dst), "l"(src));
}
#define CP_COMMIT() asm volatile("cp.async.commit_group;")
#define CP_WAIT0()  asm volatile("cp.async.wait_group 0;")

// ---------------------------------------------------------------------------
// Prep A: transpose-convert x [b][c][s] fp32 -> g_xt [b][s][c] bf16.
// ---------------------------------------------------------------------------
__global__ __launch_bounds__(256) void cvt_x_kernel(const float* __restrict__ x) {
  __shared__ float t[32][33];
  int b  = blockIdx.z;
  int s0 = blockIdx.x * 32;
  int c0 = blockIdx.y * 32;
  int tx = threadIdx.x, ty = threadIdx.y;
  const float* xb = x + (size_t)b * CC * SS;
#pragma unroll
  for (int i = 0; i < 4; i++)
    t[ty + 8 * i][tx] = xb[(size_t)(c0 + ty + 8 * i) * SS + s0 + tx];
  __syncthreads();
  uint16_t* dst = g_xt + (size_t)b * SS * CC;
#pragma unroll
  for (int i = 0; i < 4; i++) {
    float v = t[tx][ty + 8 * i];
    uint32_t p = packbf(v, v);
    dst[(size_t)(s0 + ty + 8 * i) * CC + c0 + tx] = (uint16_t)(p & 0xffffu);
  }
}

// Prep B: weights fp32 -> bf16.
__global__ __launch_bounds__(256) void cvt_w_kernel(
    const float* __restrict__ qkv_w, const float* __restrict__ proj_w) {
  int j = blockIdx.x * 256 + threadIdx.x;
  if (j < TC * CC / 2)
    ((uint32_t*)g_wq)[j] = packbf(qkv_w[2 * j], qkv_w[2 * j + 1]);
  if (j < CC * CC / 2)
    ((uint32_t*)g_wp)[j] = packbf(proj_w[2 * j], proj_w[2 * j + 1]);
}

// ---------------------------------------------------------------------------
// Kernel 1: QKV projection, bf16 mma + ldmatrix, cp.async double-buffered
// (exact R12 version). Grid: (BN*18, 12), 256 threads.
// ---------------------------------------------------------------------------
__global__ __launch_bounds__(256) void qkv_gemm_kernel(
    const float* __restrict__ bias) {
  __shared__ __align__(16) uint16_t As[2][128][40];
  __shared__ __align__(16) uint16_t Bs[2][64][40];
  int tid = threadIdx.x;
  int warp = tid >> 5, lane = tid & 31;
  int g = lane >> 2, tig = lane & 3;
  int wm = (warp & 3) * 32, wn = (warp >> 2) * 32;
  int bx = blockIdx.x;
  int b  = bx / 18;
  int m0 = (bx % 18) * 128;
  int n0 = blockIdx.y * 64;
  const uint16_t* A = g_xt + (size_t)b * SS * CC;

  uint32_t as0 = (uint32_t)__cvta_generic_to_shared(&As[0][0][0]);
  uint32_t bs0 = (uint32_t)__cvta_generic_to_shared(&Bs[0][0][0]);

  float c[2][4][4];
#pragma unroll
  for (int mt = 0; mt < 2; mt++)
#pragma unroll
    for (int nt = 0; nt < 4; nt++)
#pragma unroll
      for (int j = 0; j < 4; j++) c[mt][nt][j] = 0.f;

#define QKV_ISSUE(p, k0)                                                      \
  do {                                                                        \
    _Pragma("unroll") for (int i_ = 0; i_ < 2; i_++) {                        \
      int f_ = tid + i_ * 256;                                                \
      int m_ = f_ >> 2, cq_ = f_ & 3;                                         \
      cpa16(as0 + (p) * 10240u + (uint32_t)(m_ * 80 + cq_ * 16),              \
            &A[(size_t)(m0 + m_) * CC + (k0) + cq_ * 8]);                     \
    }                                                                         \
    {                                                                         \
      int n_ = tid >> 2, kq_ = tid & 3;                                       \
      cpa16(bs0 + (p) * 5120u + (uint32_t)(n_ * 80 + kq_ * 16),               \
            &g_wq[(size_t)(n0 + n_) * CC + (k0) + kq_ * 8]);                  \
    }                                                                         \
    CP_COMMIT();                                                              \
  } while (0)

  QKV_ISSUE(0, 0);
  for (int it = 0; it < 8; it++) {
    int p = it & 1;
    CP_WAIT0();
    __syncthreads();
    if (it < 7) QKV_ISSUE(p ^ 1, (it + 1) * 32);
    uint32_t ab = as0 + (uint32_t)p * 10240u;
    uint32_t bb = bs0 + (uint32_t)p * 5120u;
#pragma unroll
    for (int ks = 0; ks < 2; ks++) {
      uint32_t kbyte = ks * 32;
      uint32_t a[2][4];
#pragma unroll
      for (int mt = 0; mt < 2; mt++) {
        uint32_t ra = ab + (uint32_t)(wm + mt * 16 + (lane & 15)) * 80 +
                      kbyte + ((lane >> 4) & 1) * 16;
        ldmx4(a[mt][0], a[mt][1], a[mt][2], a[mt][3], ra);
      }
      uint32_t bf[4][2];
#pragma unroll
      for (int nt = 0; nt < 4; nt++) {
        uint32_t rb = bb + (uint32_t)(wn + nt * 8 + (lane & 7)) * 80 +
                      kbyte + ((lane >> 3) & 1) * 16;
        ldmx2(bf[nt][0], bf[nt][1], rb);
      }
#pragma unroll
      for (int mt = 0; mt < 2; mt++)
#pragma unroll
        for (int nt = 0; nt < 4; nt++)
          mma_bf16(c[mt][nt], a[mt][0], a[mt][1], a[mt][2], a[mt][3],
                   bf[nt][0], bf[nt][1]);
    }
    __syncthreads();
  }
#undef QKV_ISSUE

  const float scale = 0.25503489458333f;   // 32^-0.5 * log2(e)
  int nb = n0 + wn;
  int which = nb / CC;
  int hr = nb % CC;
  int h = hr >> 5;
  uint16_t* dst = (which == 0) ? g_q : (which == 1) ? g_k : g_v;
  float sc = (which == 0) ? scale : 1.f;
  long base = ((long)(b * NH + h) * SS + m0 + wm) * DD;
#pragma unroll
  for (int mt = 0; mt < 2; mt++) {
#pragma unroll
    for (int nt = 0; nt < 4; nt++) {
      int d = nt * 8 + 2 * tig;
      float b0 = bias[nb + d], b1 = bias[nb + d + 1];
      uint32_t w0 = packbf((c[mt][nt][0] + b0) * sc, (c[mt][nt][1] + b1) * sc);
      uint32_t w1 = packbf((c[mt][nt][2] + b0) * sc, (c[mt][nt][3] + b1) * sc);
      *(uint32_t*)&dst[base + (long)(mt * 16 + g) * DD + d] = w0;
      *(uint32_t*)&dst[base + (long)(mt * 16 + g + 8) * DD + d] = w1;
    }
  }
}

// ---------------------------------------------------------------------------
// Kernel 2: flash attention (R12 math: ones-column l, bf16x2 ex2, no-shift),
// restructured INTERLEAVED per 16-key chunk: QK(8 mma) -> ex2/pack -> PV(10
// mma) per chunk. Identical instruction counts and arithmetic order as R12,
// but softmax bursts are 4x shorter and sandwiched between tensor groups ->
// better cross-warp tensor-pipe overlap. pa shrinks to [2][4] (-24 regs).
// 64-key smem tiles (2 CTA/SM residency preserved). Grid: (SS/256, B*NH).
// ---------------------------------------------------------------------------
__global__ __launch_bounds__(256) void attn_kernel() {
  __shared__ __align__(16) uint32_t KsW[2][1280];   // 5120 B per buffer
  __shared__ __align__(16) uint32_t VsW[2][1280];
  int bh   = blockIdx.y;
  int tid  = threadIdx.x;
  int lane = tid & 31;
  int g = lane >> 2, tig = lane & 3;
  int q0 = blockIdx.x * 256 + (tid >> 5) * 32;

  uint32_t ks0 = (uint32_t)__cvta_generic_to_shared(&KsW[0][0]);
  uint32_t vs0 = (uint32_t)__cvta_generic_to_shared(&VsW[0][0]);
  const char* Kg = (const char*)(g_k) + (size_t)(bh * SS) * 64;  // 64B/row
  const char* Vg = (const char*)(g_v) + (size_t)(bh * SS) * 64;

  // V tail init: col 32 = 1.0bf16 (ones column for l), cols 33..39 = 0.
  // Fills only write word-cols 0..15 (64 B), so this survives the loop.
  for (int i = tid; i < 512; i += 256) {
    int buf = i >> 8, j = i & 255, rw = j >> 2, wq = j & 3;
    VsW[buf][rw * 20 + 16 + wq] = (wq == 0) ? 0x3f80u : 0u;
  }

  // Q A-fragments for 2 m-tiles (rows q0+mt*16+{g,g+8})
  const uint32_t* Qw = (const uint32_t*)(g_q) + (size_t)(bh * SS + q0) * 16;
  uint32_t qa[2][2][4];
#pragma unroll
  for (int mt = 0; mt < 2; mt++)
#pragma unroll
    for (int kc = 0; kc < 2; kc++) {
      int r = mt * 16;
      qa[mt][kc][0] = Qw[(r + g) * 16 + kc * 8 + tig];
      qa[mt][kc][1] = Qw[(r + g + 8) * 16 + kc * 8 + tig];
      qa[mt][kc][2] = Qw[(r + g) * 16 + kc * 8 + tig + 4];
      qa[mt][kc][3] = Qw[(r + g + 8) * 16 + kc * 8 + tig + 4];
    }

  float o[2][5][4];   // n-tile 4 = ones column (row sums l at col 32)
#pragma unroll
  for (int mt = 0; mt < 2; mt++)
#pragma unroll
    for (int i = 0; i < 5; i++)
#pragma unroll
      for (int j = 0; j < 4; j++) o[mt][i][j] = 0.f;

  uint32_t qk_row0 = (uint32_t)(lane & 7) * 80 + ((lane >> 3) & 1) * 16;
  uint32_t pv_row0 = (uint32_t)(lane & 15) * 80;

#define ATT_ISSUE(p, t0)                                                      \
  do {                                                                        \
    int row_ = tid >> 2, cq_ = tid & 3;                                       \
    uint32_t so_ = (uint32_t)(row_ * 80 + cq_ * 16);                          \
    size_t go_ = (size_t)((t0) + row_) * 64 + cq_ * 16;                       \
    cpa16(ks0 + (p) * 5120u + so_, Kg + go_);                                 \
    cpa16(vs0 + (p) * 5120u + so_, Vg + go_);                                 \
    CP_COMMIT();                                                              \
  } while (0)

  ATT_ISSUE(0, 0);
  for (int it = 0; it < SS / 64; it++) {
    int p = it & 1;
    CP_WAIT0();
    __syncthreads();
    if (it < SS / 64 - 1) ATT_ISSUE(p ^ 1, (it + 1) * 64);

    uint32_t qk_row = ks0 + (uint32_t)p * 5120u + qk_row0;
    uint32_t pv_row = vs0 + (uint32_t)p * 5120u + pv_row0;

    // ---- per 16-key chunk: QK -> ex2/pack -> PV (interleaved) ----
#pragma unroll
    for (int kc = 0; kc < 4; kc++) {
      uint32_t pa[2][4];
#pragma unroll
      for (int ntl = 0; ntl < 2; ntl++) {
        int nt = kc * 2 + ntl;
        float s[2][4];
#pragma unroll
        for (int mt = 0; mt < 2; mt++) {
          s[mt][0] = 0.f; s[mt][1] = 0.f; s[mt][2] = 0.f; s[mt][3] = 0.f;
        }
        uint32_t ra = qk_row + (uint32_t)(nt * 8) * 80;
#pragma unroll
        for (int dc = 0; dc < 2; dc++) {
          uint32_t b0, b1;
          ldmx2(b0, b1, ra + dc * 32);
          mma_bf16(s[0], qa[0][dc][0], qa[0][dc][1], qa[0][dc][2],
                   qa[0][dc][3], b0, b1);
          mma_bf16(s[1], qa[1][dc][0], qa[1][dc][1], qa[1][dc][2],
                   qa[1][dc][3], b0, b1);
        }
#pragma unroll
        for (int mt = 0; mt < 2; mt++) {
          pa[mt][ntl * 2]     = ex2bf2(packbf(s[mt][0], s[mt][1]));
          pa[mt][ntl * 2 + 1] = ex2bf2(packbf(s[mt][2], s[mt][3]));
        }
      }
      // PV for this 16-key chunk (5 n-tiles: 4 data + ones column for l)
      uint32_t ra = pv_row + (uint32_t)(kc * 16) * 80;
#pragma unroll
      for (int nt = 0; nt < 5; nt++) {
        uint32_t b0, b1;
        ldmx2t(b0, b1, ra + nt * 16);
        mma_bf16(o[0][nt], pa[0][0], pa[0][1], pa[0][2], pa[0][3], b0, b1);
        mma_bf16(o[1][nt], pa[1][0], pa[1][1], pa[1][2], pa[1][3], b0, b1);
      }
    }
    __syncthreads();
  }
#undef ATT_ISSUE

  int b = bh / NH, h = bh % NH;
  int src = lane & ~3;   // tig=0 lane of this quad (holds col 32 = l)
#pragma unroll
  for (int mt = 0; mt < 2; mt++) {
    float sl0 = __shfl_sync(0xffffffffu, o[mt][4][0], src);
    float sl1 = __shfl_sync(0xffffffffu, o[mt][4][2], src);
    float inv0 = 1.f / sl0, inv1 = 1.f / sl1;
    int r0 = q0 + mt * 16 + g, r1 = r0 + 8;
    uint32_t* O0 = (uint32_t*)(g_o + ((size_t)(b * SS + r0) * NH + h) * DD);
    uint32_t* O1 = (uint32_t*)(g_o + ((size_t)(b * SS + r1) * NH + h) * DD);
#pragma unroll
    for (int nt = 0; nt < 4; nt++) {
      O0[nt * 4 + tig] = packbf(o[mt][nt][0] * inv0, o[mt][nt][1] * inv0);
      O1[nt * 4 + tig] = packbf(o[mt][nt][2] * inv1, o[mt][nt][3] * inv1);
    }
  }
}

// ---------------------------------------------------------------------------
// Kernel 3: output projection, bf16 mma + ldmatrix (exact R12 version).
// Grid: (18, 4, BN), 256 threads.
// ---------------------------------------------------------------------------
__global__ __launch_bounds__(256) void proj_kernel(
    const float* __restrict__ x, const float* __restrict__ bias,
    float* __restrict__ out) {
  __shared__ __align__(16) uint16_t As[2][128][40];
  __shared__ __align__(16) uint16_t Bs[2][64][40];
  int tid = threadIdx.x;
  int warp = tid >> 5, lane = tid & 31;
  int g = lane >> 2, tig = lane & 3;
  int wm = (warp & 3) * 32, wn = (warp >> 2) * 32;
  int b  = blockIdx.z;
  int m0 = blockIdx.x * 128;
  int n0 = blockIdx.y * 64;
  const uint16_t* A = g_o + (size_t)b * SS * CC;

  uint32_t as0 = (uint32_t)__cvta_generic_to_shared(&As[0][0][0]);
  uint32_t bs0 = (uint32_t)__cvta_generic_to_shared(&Bs[0][0][0]);

  float c[2][4][4];
#pragma unroll
  for (int mt = 0; mt < 2; mt++)
#pragma unroll
    for (int nt = 0; nt < 4; nt++)
#pragma unroll
      for (int j = 0; j < 4; j++) c[mt][nt][j] = 0.f;

#define PROJ_ISSUE(p, k0)                                                     \
  do {                                                                        \
    _Pragma("unroll") for (int i_ = 0; i_ < 2; i_++) {                        \
      int f_ = tid + i_ * 256;                                                \
      int m_ = f_ >> 2, cq_ = f_ & 3;                                         \
      cpa16(as0 + (p) * 10240u + (uint32_t)(m_ * 80 + cq_ * 16),              \
            &A[(size_t)(m0 + m_) * CC + (k0) + cq_ * 8]);                     \
    }                                                                         \
    {                                                                         \
      int n_ = tid >> 2, kq_ = tid & 3;                                       \
      cpa16(bs0 + (p) * 5120u + (uint32_t)(n_ * 80 + kq_ * 16),               \
            &g_wp[(size_t)(n0 + n_) * CC + (k0) + kq_ * 8]);                  \
    }                                                                         \
    CP_COMMIT();                                                              \
  } while (0)

  PROJ_ISSUE(0, 0);
  for (int it = 0; it < 8; it++) {
    int p = it & 1;
    CP_WAIT0();
    __syncthreads();
    if (it < 7) PROJ_ISSUE(p ^ 1, (it + 1) * 32);
    uint32_t ab = as0 + (uint32_t)p * 10240u;
    uint32_t bb = bs0 + (uint32_t)p * 5120u;
#pragma unroll
    for (int ks = 0; ks < 2; ks++) {
      uint32_t kbyte = ks * 32;
      uint32_t a[2][4];
#pragma unroll
      for (int mt = 0; mt < 2; mt++) {
        uint32_t ra = ab + (uint32_t)(wm + mt * 16 + (lane & 15)) * 80 +
                      kbyte + ((lane >> 4) & 1) * 16;
        ldmx4(a[mt][0], a[mt][1], a[mt][2], a[mt][3], ra);
      }
      uint32_t bf[4][2];
#pragma unroll
      for (int nt = 0; nt < 4; nt++) {
        uint32_t rb = bb + (uint32_t)(wn + nt * 8 + (lane & 7)) * 80 +
                      kbyte + ((lane >> 3) & 1) * 16;
        ldmx2(bf[nt][0], bf[nt][1], rb);
      }
#pragma unroll
      for (int mt = 0; mt < 2; mt++)
#pragma unroll
        for (int nt = 0; nt < 4; nt++)
          mma_bf16(c[mt][nt], a[mt][0], a[mt][1], a[mt][2], a[mt][3],
                   bf[nt][0], bf[nt][1]);
    }
    __syncthreads();
  }
#undef PROJ_ISSUE

#pragma unroll
  for (int nt = 0; nt < 4; nt++) {
    int n = n0 + wn + nt * 8 + 2 * tig;
    float b0 = bias[n], b1 = bias[n + 1];
    long col0 = (long)(b * CC + n) * SS;
    long col1 = col0 + SS;
#pragma unroll
    for (int mt = 0; mt < 2; mt++) {
      int s = m0 + wm + mt * 16 + g;
      out[col0 + s]     = c[mt][nt][0] + b0 + x[col0 + s];
      out[col1 + s]     = c[mt][nt][1] + b1 + x[col1 + s];
      out[col0 + s + 8] = c[mt][nt][2] + b0 + x[col0 + s + 8];
      out[col1 + s + 8] = c[mt][nt][3] + b1 + x[col1 + s + 8];
    }
  }
}

// ---------------------------------------------------------------------------
extern "C" void kernel_launch(void* const* d_in, const int* in_sizes, int n_in,
                              void* d_out, int out_size) {
  const float* x      = (const float*)d_in[0];
  const float* qkv_w  = (const float*)d_in[1];
  const float* qkv_b  = (const float*)d_in[2];
  const float* proj_w = (const float*)d_in[3];
  const float* proj_b = (const float*)d_in[4];
  float* out = (float*)d_out;

  cvt_x_kernel<<<dim3(SS / 32, CC / 32, BN), dim3(32, 8)>>>(x);
  cvt_w_kernel<<<dim3((TC * CC / 2 + 255) / 256), 256>>>(qkv_w, proj_w);
  qkv_gemm_kernel<<<dim3(BN * 18, TC / 64), 256>>>(qkv_b);
  attn_kernel<<<dim3(SS / 256, BN * NH), 256>>>();
  proj_kernel<<<dim3(18, CC / 64, BN), 256>>>(x, proj_b, out);
}